// round 15
// baseline (speedup 1.0000x reference)
#include <cuda_runtime.h>
#include <cuda_bf16.h>
#include <cstdint>

#define Q  4
#define K  4096
#define D  256
#define NTOK_MAX 32768
#define NX_MAX   (NTOK_MAX * D)
#define CB_ELEMS (Q * K * D)
#define SCORE_OFFSET 1024.0f
#define BLK_B   33024              // 64 codes x 512B swizzled + 64 c2 floats
#define NCHUNK  64                 // 64-code chunks per layer

// ---------------- device scratch (allocation-free rule) ----------------
// g_rb: bf16 residual pre-swizzled in 32KB blocks of 64 tokens:
//   byte = (tok>>6)*32768 + (tok&63)*512 + ((c16 ^ (tok&7))<<4)
// g_cbbA: per layer 64 blocks of [64 codes swizzled bf16 (32768B) | 64 c2+off
//   floats (256B)] so one cp.async.bulk delivers codes AND their c2 slice.
__device__ float                       g_res[NX_MAX];       // fp32 linear
__device__ __align__(16) __nv_bfloat16 g_rb[NX_MAX];        // bf16 swizzled
__device__ __align__(16) char          g_cbbA[Q * NCHUNK * BLK_B];
__device__ float                       g_c2[Q * K];
__device__ float                       g_loss[Q];

// ---------------- helpers ----------------
__device__ __forceinline__ uint32_t smem_u32(const void* p) {
    uint32_t a;
    asm("{ .reg .u64 t; cvta.to.shared.u64 t, %1; cvt.u32.u64 %0, t; }"
        : "=r"(a) : "l"(p));
    return a;
}
__device__ __forceinline__ unsigned long long pack_key(float s, int code) {
    unsigned u = __float_as_uint(s);
    u = (u & 0x80000000u) ? ~u : (u | 0x80000000u);
    return ((unsigned long long)u << 32) | (unsigned)code;
}
__device__ __forceinline__ void mbar_init(uint32_t m, uint32_t cnt) {
    asm volatile("mbarrier.init.shared.b64 [%0], %1;" :: "r"(m), "r"(cnt) : "memory");
}
__device__ __forceinline__ void mbar_arrive(uint32_t m) {
    asm volatile("mbarrier.arrive.shared.b64 _, [%0];" :: "r"(m) : "memory");
}
__device__ __forceinline__ void expect_tx(uint32_t m, uint32_t bytes) {
    asm volatile("mbarrier.arrive.expect_tx.shared.b64 _, [%0], %1;"
                 :: "r"(m), "r"(bytes) : "memory");
}
__device__ __forceinline__ void bulk_cp(uint32_t dst, const void* src,
                                        uint32_t bytes, uint32_t mbar) {
    asm volatile(
        "cp.async.bulk.shared::cta.global.mbarrier::complete_tx::bytes "
        "[%0], [%1], %2, [%3];"
        :: "r"(dst), "l"(src), "r"(bytes), "r"(mbar) : "memory");
}
__device__ __forceinline__ void wait_parity(uint32_t m, uint32_t ph) {
    asm volatile(
        "{\n\t.reg .pred P;\n\t"
        "W%=:\n\t"
        "mbarrier.try_wait.parity.acquire.cta.shared::cta.b64 P, [%0], %1, 0x989680;\n\t"
        "@P bra D%=;\n\t"
        "bra W%=;\n\t"
        "D%=:\n\t}"
        :: "r"(m), "r"(ph) : "memory");
}
__device__ __forceinline__ void ldsm_x4(uint32_t& r0, uint32_t& r1,
                                        uint32_t& r2, uint32_t& r3, uint32_t a) {
    asm volatile("ldmatrix.sync.aligned.m8n8.x4.shared.b16 {%0,%1,%2,%3}, [%4];"
                 : "=r"(r0), "=r"(r1), "=r"(r2), "=r"(r3) : "r"(a));
}
__device__ __forceinline__ void mma16816(float* d, const uint32_t* a,
                                         const uint32_t* b) {
    asm volatile(
        "mma.sync.aligned.m16n8k16.row.col.f32.bf16.bf16.f32 "
        "{%0,%1,%2,%3},{%4,%5,%6,%7},{%8,%9},{%0,%1,%2,%3};"
        : "+f"(d[0]), "+f"(d[1]), "+f"(d[2]), "+f"(d[3])
        : "r"(a[0]), "r"(a[1]), "r"(a[2]), "r"(a[3]), "r"(b[0]), "r"(b[1]));
}
__device__ __forceinline__ uint4 pack8(float4 a, float4 b) {
    __nv_bfloat162 p0 = __floats2bfloat162_rn(a.x, a.y);
    __nv_bfloat162 p1 = __floats2bfloat162_rn(a.z, a.w);
    __nv_bfloat162 p2 = __floats2bfloat162_rn(b.x, b.y);
    __nv_bfloat162 p3 = __floats2bfloat162_rn(b.z, b.w);
    uint4 r;
    r.x = *reinterpret_cast<uint32_t*>(&p0);
    r.y = *reinterpret_cast<uint32_t*>(&p1);
    r.z = *reinterpret_cast<uint32_t*>(&p2);
    r.w = *reinterpret_cast<uint32_t*>(&p3);
    return r;
}
// 64-row-block swizzled offset (row = token or code, c16 = 16B column group)
__device__ __forceinline__ uint32_t sw64(int row, int c16) {
    return (uint32_t)((row >> 6) * 32768) + (uint32_t)((row & 63) * 512)
         + (uint32_t)(((c16 ^ (row & 7)) << 4));
}
__device__ __forceinline__ void ins2f(float k, unsigned id,
                                      float& t0, unsigned& i0,
                                      float& t1, unsigned& i1) {
    bool p0 = k < t0;
    bool p1 = k < t1;
    float    nt1 = p1 ? k  : t1;
    unsigned ni1 = p1 ? id : i1;
    t1 = p0 ? t0 : nt1;
    i1 = p0 ? i0 : ni1;
    t0 = fminf(t0, k);
    i0 = p0 ? id : i0;
}

// ---------------------------------------------------------------------------
__global__ void copy_res_kernel(const float* __restrict__ x, int ngrp) {
    int i = blockIdx.x * blockDim.x + threadIdx.x;
    if (i >= ngrp) return;
    float4 v0 = reinterpret_cast<const float4*>(x)[i * 2];
    float4 v1 = reinterpret_cast<const float4*>(x)[i * 2 + 1];
    reinterpret_cast<float4*>(g_res)[i * 2]     = v0;
    reinterpret_cast<float4*>(g_res)[i * 2 + 1] = v1;
    int t = i >> 5, c = i & 31;
    *reinterpret_cast<uint4*>(reinterpret_cast<char*>(g_rb) + sw64(t, c)) =
        pack8(v0, v1);
}

// exact ||c||^2 and zero losses
__global__ void c2_kernel(const float* __restrict__ cb) {
    if (blockIdx.x == 0 && threadIdx.x < Q) g_loss[threadIdx.x] = 0.f;
    int row  = blockIdx.x * 8 + (threadIdx.x >> 5);
    int lane = threadIdx.x & 31;
    const float* p = cb + (size_t)row * D;
    float s = 0.f;
#pragma unroll
    for (int t = 0; t < 2; t++) {
        float4 v = *reinterpret_cast<const float4*>(p + lane * 4 + t * 128);
        s += v.x * v.x + v.y * v.y + v.z * v.z + v.w * v.w;
    }
#pragma unroll
    for (int o = 16; o; o >>= 1) s += __shfl_down_sync(0xFFFFFFFFu, s, o);
    if (!lane) g_c2[row] = s;
}

// codebook -> augmented blocks (swizzled bf16 + offset c2 floats).
// Must run AFTER c2_kernel (reads g_c2).
__global__ void split_cb_kernel(const float* __restrict__ cb, int ngrp) {
    int i = blockIdx.x * blockDim.x + threadIdx.x;
    if (i >= ngrp) return;
    float4 v0 = reinterpret_cast<const float4*>(cb)[i * 2];
    float4 v1 = reinterpret_cast<const float4*>(cb)[i * 2 + 1];
    int rowg = i >> 5, c = i & 31;          // rowg = l*4096 + code
    int l = rowg >> 12, code = rowg & 4095;
    char* blk = g_cbbA + (size_t)(l * NCHUNK + (code >> 6)) * BLK_B;
    int r = code & 63;
    *reinterpret_cast<uint4*>(blk + r * 512 + ((c ^ (r & 7)) << 4)) =
        pack8(v0, v1);
    if (c == 0)
        *reinterpret_cast<float*>(blk + 32768 + r * 4) =
            g_c2[rowg] + SCORE_OFFSET;
}

// ---------------------------------------------------------------------------
// Fused coarse + rescore + update. CTA = 64 tokens x 4096 codes; 8 warps
// (2M x 4N, warp tile 32x16); 64 chunks of 64 codes; double-buffered
// cp.async.bulk of augmented (B|c2) blocks. 2 CTAs/SM (~99KB smem each).
// RACE RULE: no thread reads a double-buffered byte after its drain-arrive —
// c2 values are hoisted into registers right after the fill-wait.
#define A_OFF    0
#define B_OFF    32768
#define BUF_SZ   BLK_B
#define MB_OFF   (B_OFF + 2 * BUF_SZ)            // 98816
#define CAND_OFF (MB_OFF + 64)
#define LOSS_OFF (CAND_OFF + 64 * 8 * 4)
#define SMEM_SZ  (LOSS_OFF + 64 * 4)             // ~99KB
#define CTHREADS 256

__global__ __launch_bounds__(CTHREADS, 2)
void coarse_kernel(const float* __restrict__ cbF, float* __restrict__ out,
                   int layer, int n_tok, int idx_base) {
    extern __shared__ char smem[];
    const int tid  = threadIdx.x;
    const int lane = tid & 31, wid = tid >> 5;        // 8 warps
    const int warpM = wid >> 2, warpN = wid & 3;      // 2M x 4N
    const int tokbase = blockIdx.x * 64;

    const uint32_t sb   = smem_u32(smem);
    const uint32_t a_sm = sb + A_OFF;
    const uint32_t b_sm = sb + B_OFF;
    const uint32_t mb   = sb + MB_OFF;  // fill0, fill1, drain0, drain1, ambar
    unsigned* cand_sm = reinterpret_cast<unsigned*>(smem + CAND_OFF);
    float*    loss_sm = reinterpret_cast<float*>(smem + LOSS_OFF);

    const char* cbA = g_cbbA + (size_t)layer * NCHUNK * BLK_B;

    if (tid == 0) {
        mbar_init(mb + 0, 1);    // fill buf0 (expect_tx)
        mbar_init(mb + 8, 1);    // fill buf1
        mbar_init(mb + 16, 8);   // drain buf0 (8 warps)
        mbar_init(mb + 24, 8);   // drain buf1
        mbar_init(mb + 32, 1);   // A tile
        asm volatile("fence.proxy.async.shared::cta;" ::: "memory");
        expect_tx(mb + 32, 32768);
        bulk_cp(a_sm, reinterpret_cast<const char*>(g_rb)
                        + (size_t)(tokbase >> 6) * 32768, 32768, mb + 32);
        expect_tx(mb + 0, BLK_B);
        bulk_cp(b_sm, cbA, BLK_B, mb + 0);
        expect_tx(mb + 8, BLK_B);
        bulk_cp(b_sm + BUF_SZ, cbA + BLK_B, BLK_B, mb + 8);
    }
    __syncthreads();
    wait_parity(mb + 32, 0);   // A tile resident

    // lane geometry for ldmatrix
    const int lrow  = ((lane >> 3) & 1) * 8 + (lane & 7);
    const int khalf = lane >> 4;
    uint32_t a_base[2]; int a_s7[2];
#pragma unroll
    for (int mi = 0; mi < 2; mi++) {
        int row = warpM * 32 + mi * 16 + lrow;
        a_base[mi] = a_sm + row * 512;
        a_s7[mi]   = row & 7;
    }
    const int brow = warpN * 16 + lrow;
    const uint32_t b_off = (uint32_t)(brow * 512);
    const int b_s7 = brow & 7;
    const int innerbase = warpN * 16 + 2 * (lane & 3);   // c2 column base

    // running top-2 (float keys) + code ids, 4 token-row slots (mi x h)
    float    t0[4], t1[4];
    unsigned i0[4], i1[4];
#pragma unroll
    for (int s = 0; s < 4; s++) {
        t0[s] = __int_as_float(0x7f800000);
        t1[s] = __int_as_float(0x7f800000);
        i0[s] = 0u; i1[s] = 0u;
    }

    for (int ci = 0; ci < NCHUNK; ci++) {
        const int b  = ci & 1;
        const uint32_t ph = (unsigned)((ci >> 1) & 1);

        wait_parity(mb + b * 8, ph);               // chunk ci resident

        // hoist c2 values into registers BEFORE drain-arrive (race rule)
        const float* c2p = reinterpret_cast<const float*>(
            smem + B_OFF + b * BUF_SZ + 32768);
        float2 c2v0 = *reinterpret_cast<const float2*>(c2p + innerbase);
        float2 c2v1 = *reinterpret_cast<const float2*>(c2p + innerbase + 8);

        const uint32_t bbase = b_sm + b * BUF_SZ;
        float acc[2][2][4];
#pragma unroll
        for (int mi = 0; mi < 2; mi++)
#pragma unroll
            for (int nt = 0; nt < 2; nt++)
#pragma unroll
                for (int v = 0; v < 4; v++) acc[mi][nt][v] = 0.f;

#pragma unroll
        for (int ks = 0; ks < 16; ks++) {
            const int c = ks * 2 + khalf;
            uint32_t a[2][4];
#pragma unroll
            for (int mi = 0; mi < 2; mi++)
                ldsm_x4(a[mi][0], a[mi][1], a[mi][2], a[mi][3],
                        a_base[mi] + ((c ^ a_s7[mi]) << 4));
            uint32_t r0, r1, r2, r3;
            ldsm_x4(r0, r1, r2, r3, bbase + b_off + ((c ^ b_s7) << 4));
            uint32_t b2[2][2];
            b2[0][0] = r0; b2[0][1] = r2;
            b2[1][0] = r1; b2[1][1] = r3;
#pragma unroll
            for (int mi = 0; mi < 2; mi++)
#pragma unroll
                for (int nt = 0; nt < 2; nt++)
                    mma16816(acc[mi][nt], a[mi], b2[nt]);
        }
        if (lane == 0) mbar_arrive(mb + 16 + b * 8);   // all buf-b reads done

        // epilogue: pairwise-min + exact-key top-2 (register-resident c2)
#pragma unroll
        for (int nt = 0; nt < 2; nt++) {
            const int col = ci * 64 + innerbase + nt * 8;
            float2 c2v = nt ? c2v1 : c2v0;
#pragma unroll
            for (int mi = 0; mi < 2; mi++)
#pragma unroll
                for (int h = 0; h < 2; h++) {
                    float s0 = fmaf(-2.f, acc[mi][nt][h * 2 + 0], c2v.x);
                    float s1 = fmaf(-2.f, acc[mi][nt][h * 2 + 1], c2v.y);
                    float    pmn = fminf(s0, s1);
                    unsigned pid = (s0 <= s1) ? (unsigned)col
                                              : (unsigned)(col + 1);
                    const int s = mi * 2 + h;
                    ins2f(pmn, pid, t0[s], i0[s], t1[s], i1[s]);
                }
        }

        if (ci < NCHUNK - 2 && tid == 0) {
            wait_parity(mb + 16 + b * 8, ph);      // all warps drained buf b
            expect_tx(mb + b * 8, BLK_B);
            bulk_cp(b_sm + b * BUF_SZ, cbA + (size_t)(ci + 2) * BLK_B,
                    BLK_B, mb + b * 8);
        }
    }

    // quad merge; 2 candidates per warpN group per token into smem
#pragma unroll
    for (int s = 0; s < 4; s++) {
        float    a0 = t0[s], a1 = t1[s];
        unsigned b0 = i0[s], b1 = i1[s];
#pragma unroll
        for (int o = 1; o <= 2; o <<= 1) {
            float    q0  = __shfl_xor_sync(0xFFFFFFFFu, a0, o);
            unsigned qi0 = __shfl_xor_sync(0xFFFFFFFFu, b0, o);
            float    q1  = __shfl_xor_sync(0xFFFFFFFFu, a1, o);
            unsigned qi1 = __shfl_xor_sync(0xFFFFFFFFu, b1, o);
            ins2f(q0, qi0, a0, b0, a1, b1);
            ins2f(q1, qi1, a0, b0, a1, b1);
        }
        if ((lane & 3) == 0) {
            int ltok = warpM * 32 + (s >> 1) * 16 + (s & 1) * 8 + (lane >> 2);
            cand_sm[ltok * 8 + warpN * 2]     = b0;
            cand_sm[ltok * 8 + warpN * 2 + 1] = b1;
        }
    }
    __syncthreads();

    // -------- fused tail: exact fp32 rescore + update; warp -> 8 tokens -----
    const float* cbL = cbF + (size_t)layer * K * D;
#pragma unroll 1
    for (int tt = 0; tt < 8; tt++) {
        const int ltok  = wid * 8 + tt;
        const int token = tokbase + ltok;
        unsigned mycode = cand_sm[ltok * 8 + (lane & 7)];

        float* rp = g_res + (size_t)token * D + lane * 8;
        float4 r0 = *reinterpret_cast<const float4*>(rp);
        float4 r1 = *reinterpret_cast<const float4*>(rp + 4);

        unsigned long long best = ~0ull;
#pragma unroll
        for (int half = 0; half < 2; half++) {
            int codes[4];
            float4 c0[4], c1[4];
#pragma unroll
            for (int j = 0; j < 4; j++) {
                codes[j] = (int)__shfl_sync(0xFFFFFFFFu, mycode, half * 4 + j);
                const float* c = cbL + (size_t)codes[j] * D + lane * 8;
                c0[j] = *reinterpret_cast<const float4*>(c);
                c1[j] = *reinterpret_cast<const float4*>(c + 4);
            }
            float dot[4];
#pragma unroll
            for (int j = 0; j < 4; j++) {
                float d0 = r0.x * c0[j].x;
                d0 = fmaf(r0.y, c0[j].y, d0); d0 = fmaf(r0.z, c0[j].z, d0);
                d0 = fmaf(r0.w, c0[j].w, d0); d0 = fmaf(r1.x, c1[j].x, d0);
                d0 = fmaf(r1.y, c1[j].y, d0); d0 = fmaf(r1.z, c1[j].z, d0);
                d0 = fmaf(r1.w, c1[j].w, d0);
                dot[j] = d0;
            }
#pragma unroll
            for (int o = 16; o; o >>= 1)
#pragma unroll
                for (int j = 0; j < 4; j++)
                    dot[j] += __shfl_xor_sync(0xFFFFFFFFu, dot[j], o);
#pragma unroll
            for (int j = 0; j < 4; j++) {
                float score = fmaf(-2.f, dot[j], g_c2[layer * K + codes[j]]);
                unsigned long long key = pack_key(score, codes[j]);
                best = key < best ? key : best;
            }
        }
        int idx = (int)(unsigned)(best & 0xFFFFFFFFull);

        const float* q = cbL + (size_t)idx * D + lane * 8;
        float4 q0 = *reinterpret_cast<const float4*>(q);
        float4 q1 = *reinterpret_cast<const float4*>(q + 4);
        r0.x -= q0.x; r0.y -= q0.y; r0.z -= q0.z; r0.w -= q0.w;
        r1.x -= q1.x; r1.y -= q1.y; r1.z -= q1.z; r1.w -= q1.w;
        *reinterpret_cast<float4*>(rp)     = r0;
        *reinterpret_cast<float4*>(rp + 4) = r1;
        if (layer < Q - 1) {
            *reinterpret_cast<uint4*>(
                reinterpret_cast<char*>(g_rb) + sw64(token, lane)) =
                pack8(r0, r1);
        }
        float local = r0.x * r0.x + r0.y * r0.y + r0.z * r0.z + r0.w * r0.w
                    + r1.x * r1.x + r1.y * r1.y + r1.z * r1.z + r1.w * r1.w;
#pragma unroll
        for (int o = 16; o; o >>= 1)
            local += __shfl_down_sync(0xFFFFFFFFu, local, o);
        if (!lane) {
            out[idx_base + layer * n_tok + token] = (float)idx;
            loss_sm[ltok] = local;
        }
    }
    __syncthreads();
    if (wid == 0) {
        float s = loss_sm[lane] + loss_sm[lane + 32];
#pragma unroll
        for (int o = 16; o; o >>= 1) s += __shfl_down_sync(0xFFFFFFFFu, s, o);
        if (!lane) atomicAdd(&g_loss[layer], s);
    }
}

// ---------------------------------------------------------------------------
__global__ void finalize_kernel(const float* __restrict__ x,
                                float* __restrict__ out,
                                int nx4, int loss_off, float invND) {
    int i = blockIdx.x * blockDim.x + threadIdx.x;
    if (i < nx4) {
        float4 xv = reinterpret_cast<const float4*>(x)[i];
        float4 rv = reinterpret_cast<const float4*>(g_res)[i];
        float4 o;
        o.x = xv.x - rv.x; o.y = xv.y - rv.y;
        o.z = xv.z - rv.z; o.w = xv.w - rv.w;
        reinterpret_cast<float4*>(out)[i] = o;
    }
    if (blockIdx.x == 0 && threadIdx.x < Q)
        out[loss_off + threadIdx.x] = g_loss[threadIdx.x] * invND;
}

// ---------------------------------------------------------------------------
extern "C" void kernel_launch(void* const* d_in, const int* in_sizes, int n_in,
                              void* d_out, int out_size) {
    const float* x  = (const float*)d_in[0];   // [8, 4096, 256] fp32
    const float* cb = (const float*)d_in[1];   // [4, 4096, 256] fp32
    float* out = (float*)d_out;

    int nx    = in_sizes[0];      // 8388608
    int n_tok = nx / D;           // 32768
    int nx4   = nx / 4;
    int ngrp  = nx / 8;

    cudaFuncSetAttribute(coarse_kernel,
                         cudaFuncAttributeMaxDynamicSharedMemorySize, SMEM_SZ);

    copy_res_kernel<<<(ngrp + 255) / 256, 256>>>(x, ngrp);
    c2_kernel<<<(Q * K) / 8, 256>>>(cb);
    split_cb_kernel<<<(CB_ELEMS / 8 + 255) / 256, 256>>>(cb, CB_ELEMS / 8);

    for (int qi = 0; qi < Q; qi++)
        coarse_kernel<<<n_tok / 64, CTHREADS, SMEM_SZ>>>(cb, out, qi, n_tok, nx);

    finalize_kernel<<<(nx4 + 255) / 256, 256>>>(
        x, out, nx4, nx + Q * n_tok, 1.f / (float)nx);
}

// round 16
// speedup vs baseline: 1.0499x; 1.0499x over previous
#include <cuda_runtime.h>
#include <cuda_bf16.h>
#include <cstdint>

#define Q  4
#define K  4096
#define D  256
#define NTOK_MAX 32768
#define NX_MAX   (NTOK_MAX * D)
#define CB_ELEMS (Q * K * D)
#define SCORE_OFFSET 1024.0f

// ---------------- device scratch (allocation-free rule) ----------------
// g_rb / g_cbb hold bf16 data PRE-SWIZZLED in 64KB blocks (128 rows x 256
// cols; within block: row*512 + ((c16 ^ (row&7))<<4)) so a linear
// cp.async.bulk into smem lands in ldmatrix-ready swizzled layout.
__device__ float                             g_res[NX_MAX];   // fp32 linear
__device__ __align__(16) __nv_bfloat16       g_rb[NX_MAX];    // bf16 swizzled
__device__ __align__(16) __nv_bfloat16       g_cbb[CB_ELEMS]; // bf16 swizzled
__device__ float                             g_c2[Q * K];
__device__ float                             g_loss[Q];

// ---------------- helpers ----------------
__device__ __forceinline__ uint32_t smem_u32(const void* p) {
    uint32_t a;
    asm("{ .reg .u64 t; cvta.to.shared.u64 t, %1; cvt.u32.u64 %0, t; }"
        : "=r"(a) : "l"(p));
    return a;
}
__device__ __forceinline__ unsigned long long pack_key(float s, int code) {
    unsigned u = __float_as_uint(s);
    u = (u & 0x80000000u) ? ~u : (u | 0x80000000u);
    return ((unsigned long long)u << 32) | (unsigned)code;
}
__device__ __forceinline__ void mbar_init(uint32_t m, uint32_t cnt) {
    asm volatile("mbarrier.init.shared.b64 [%0], %1;" :: "r"(m), "r"(cnt) : "memory");
}
__device__ __forceinline__ void mbar_arrive(uint32_t m) {
    asm volatile("mbarrier.arrive.shared.b64 _, [%0];" :: "r"(m) : "memory");
}
__device__ __forceinline__ void expect_tx(uint32_t m, uint32_t bytes) {
    asm volatile("mbarrier.arrive.expect_tx.shared.b64 _, [%0], %1;"
                 :: "r"(m), "r"(bytes) : "memory");
}
__device__ __forceinline__ void bulk_cp(uint32_t dst, const void* src,
                                        uint32_t bytes, uint32_t mbar) {
    asm volatile(
        "cp.async.bulk.shared::cta.global.mbarrier::complete_tx::bytes "
        "[%0], [%1], %2, [%3];"
        :: "r"(dst), "l"(src), "r"(bytes), "r"(mbar) : "memory");
}
__device__ __forceinline__ void wait_parity(uint32_t m, uint32_t ph) {
    asm volatile(
        "{\n\t.reg .pred P;\n\t"
        "W%=:\n\t"
        "mbarrier.try_wait.parity.acquire.cta.shared::cta.b64 P, [%0], %1, 0x989680;\n\t"
        "@P bra D%=;\n\t"
        "bra W%=;\n\t"
        "D%=:\n\t}"
        :: "r"(m), "r"(ph) : "memory");
}
__device__ __forceinline__ void ldsm_x4(uint32_t& r0, uint32_t& r1,
                                        uint32_t& r2, uint32_t& r3, uint32_t a) {
    asm volatile("ldmatrix.sync.aligned.m8n8.x4.shared.b16 {%0,%1,%2,%3}, [%4];"
                 : "=r"(r0), "=r"(r1), "=r"(r2), "=r"(r3) : "r"(a));
}
__device__ __forceinline__ void mma16816(float* d, const uint32_t* a,
                                         const uint32_t* b) {
    asm volatile(
        "mma.sync.aligned.m16n8k16.row.col.f32.bf16.bf16.f32 "
        "{%0,%1,%2,%3},{%4,%5,%6,%7},{%8,%9},{%0,%1,%2,%3};"
        : "+f"(d[0]), "+f"(d[1]), "+f"(d[2]), "+f"(d[3])
        : "r"(a[0]), "r"(a[1]), "r"(a[2]), "r"(a[3]), "r"(b[0]), "r"(b[1]));
}
__device__ __forceinline__ uint4 pack8(float4 a, float4 b) {
    __nv_bfloat162 p0 = __floats2bfloat162_rn(a.x, a.y);
    __nv_bfloat162 p1 = __floats2bfloat162_rn(a.z, a.w);
    __nv_bfloat162 p2 = __floats2bfloat162_rn(b.x, b.y);
    __nv_bfloat162 p3 = __floats2bfloat162_rn(b.z, b.w);
    uint4 r;
    r.x = *reinterpret_cast<uint32_t*>(&p0);
    r.y = *reinterpret_cast<uint32_t*>(&p1);
    r.z = *reinterpret_cast<uint32_t*>(&p2);
    r.w = *reinterpret_cast<uint32_t*>(&p3);
    return r;
}
// 128-row-block swizzled offset (row, c16 = 16B column group 0..31)
__device__ __forceinline__ uint32_t sw_off(int row, int c16) {
    return (uint32_t)((row >> 7) * 65536) + (uint32_t)((row & 127) * 512)
         + (uint32_t)(((c16 ^ (row & 7)) << 4));
}
__device__ __forceinline__ void ins2f(float k, unsigned id,
                                      float& t0, unsigned& i0,
                                      float& t1, unsigned& i1) {
    bool p0 = k < t0;
    bool p1 = k < t1;
    float    nt1 = p1 ? k  : t1;
    unsigned ni1 = p1 ? id : i1;
    t1 = p0 ? t0 : nt1;
    i1 = p0 ? i0 : ni1;
    t0 = fminf(t0, k);
    i0 = p0 ? id : i0;
}

// ---------------------------------------------------------------------------
// bf16 swizzled mirror of x (fp32 residual is materialized by layer-0 tail)
__global__ void init_rb_kernel(const float* __restrict__ x, int ngrp) {
    int i = blockIdx.x * blockDim.x + threadIdx.x;
    if (i >= ngrp) return;
    float4 v0 = reinterpret_cast<const float4*>(x)[i * 2];
    float4 v1 = reinterpret_cast<const float4*>(x)[i * 2 + 1];
    int t = i >> 5, c = i & 31;
    *reinterpret_cast<uint4*>(reinterpret_cast<char*>(g_rb) + sw_off(t, c)) =
        pack8(v0, v1);
}

// exact ||c||^2 + swizzled bf16 codebook, one warp per row; zero losses
__global__ void c2_split_kernel(const float* __restrict__ cb) {
    if (blockIdx.x == 0 && threadIdx.x < Q) g_loss[threadIdx.x] = 0.f;
    int row  = blockIdx.x * 8 + (threadIdx.x >> 5);
    int lane = threadIdx.x & 31;
    const float* p = cb + (size_t)row * D + lane * 8;
    float4 v0 = *reinterpret_cast<const float4*>(p);
    float4 v1 = *reinterpret_cast<const float4*>(p + 4);
    *reinterpret_cast<uint4*>(reinterpret_cast<char*>(g_cbb) + sw_off(row, lane)) =
        pack8(v0, v1);
    float s = v0.x * v0.x + v0.y * v0.y + v0.z * v0.z + v0.w * v0.w
            + v1.x * v1.x + v1.y * v1.y + v1.z * v1.z + v1.w * v1.w;
#pragma unroll
    for (int o = 16; o; o >>= 1) s += __shfl_down_sync(0xFFFFFFFFu, s, o);
    if (!lane) g_c2[row] = s;
}

// ---------------------------------------------------------------------------
// Fused coarse + rescore + update (R13 champion shape).
// 16 warps (4M x 4N), warp tile 32x32; 32 code chunks of 128; B refilled by
// cp.async.bulk from pre-swizzled gmem; pairwise-min exact-key top-2.
// Layer 0 reads residual from x; layer Q-1 writes out = x - r directly.
#define A_OFF    16384
#define B_OFF    (A_OFF + 65536)
#define BUF_SZ   65536
#define MB_OFF   (B_OFF + 2 * BUF_SZ)
#define CAND_OFF (MB_OFF + 64)
#define LOSS_OFF (CAND_OFF + 128 * 8 * 4)
#define SMEM_SZ  (LOSS_OFF + 128 * 4)
#define CTHREADS 512

__global__ __launch_bounds__(CTHREADS, 1)
void coarse_kernel(const float* __restrict__ cbF, const float* __restrict__ x,
                   float* __restrict__ out, int layer, int n_tok, int idx_base) {
    extern __shared__ char smem[];
    const int tid  = threadIdx.x;
    const int lane = tid & 31, wid = tid >> 5;
    const int warpM = wid >> 2, warpN = wid & 3;
    const int tokbase = blockIdx.x * 128;

    const uint32_t sb   = smem_u32(smem);
    const uint32_t a_sm = sb + A_OFF;
    const uint32_t b_sm = sb + B_OFF;
    const uint32_t mb   = sb + MB_OFF;  // fill0, fill1, drain0, drain1, ambar
    float*    c2s     = reinterpret_cast<float*>(smem);
    unsigned* cand_sm = reinterpret_cast<unsigned*>(smem + CAND_OFF);
    float*    loss_sm = reinterpret_cast<float*>(smem + LOSS_OFF);

    const __nv_bfloat16* cbB = g_cbb + (size_t)layer * K * D;  // swizzled

    if (tid == 0) {
        mbar_init(mb + 0, 1);     // fill buf0 (expect_tx)
        mbar_init(mb + 8, 1);     // fill buf1
        mbar_init(mb + 16, 16);   // drain buf0 (16 warps)
        mbar_init(mb + 24, 16);   // drain buf1
        mbar_init(mb + 32, 1);    // A tile
        asm volatile("fence.proxy.async.shared::cta;" ::: "memory");
        expect_tx(mb + 32, 65536);
        bulk_cp(a_sm, g_rb + (size_t)tokbase * D, 65536, mb + 32);
        expect_tx(mb + 0, 65536);
        bulk_cp(b_sm, cbB, 65536, mb + 0);
        expect_tx(mb + 8, 65536);
        bulk_cp(b_sm + BUF_SZ, cbB + 32768, 65536, mb + 8);
    }
    for (int i = tid; i < 4096; i += CTHREADS)
        c2s[i] = g_c2[layer * K + i] + SCORE_OFFSET;
    __syncthreads();
    wait_parity(mb + 32, 0);   // A tile resident

    // lane geometry for ldmatrix
    const int lrow  = ((lane >> 3) & 1) * 8 + (lane & 7);
    const int khalf = lane >> 4;
    uint32_t a_base[2]; int a_s7[2];
#pragma unroll
    for (int mi = 0; mi < 2; mi++) {
        int row = warpM * 32 + mi * 16 + lrow;
        a_base[mi] = a_sm + row * 512;
        a_s7[mi]   = row & 7;
    }
    uint32_t b_off[2]; int b_s7[2];
#pragma unroll
    for (int p = 0; p < 2; p++) {
        int row = warpN * 32 + p * 16 + lrow;
        b_off[p] = row * 512;
        b_s7[p]  = row & 7;
    }

    // running top-2 (float keys) + code ids, 4 token-row slots (mi x h)
    float    t0[4], t1[4];
    unsigned i0[4], i1[4];
#pragma unroll
    for (int s = 0; s < 4; s++) {
        t0[s] = __int_as_float(0x7f800000);
        t1[s] = __int_as_float(0x7f800000);
        i0[s] = 0u; i1[s] = 0u;
    }

    for (int ci = 0; ci < 32; ci++) {
        const int b  = ci & 1;
        const uint32_t ph = (unsigned)((ci >> 1) & 1);

        wait_parity(mb + b * 8, ph);               // chunk ci data resident

        const uint32_t bbase = b_sm + b * BUF_SZ;
        float acc[2][4][4];
#pragma unroll
        for (int mi = 0; mi < 2; mi++)
#pragma unroll
            for (int nt = 0; nt < 4; nt++)
#pragma unroll
                for (int v = 0; v < 4; v++) acc[mi][nt][v] = 0.f;

#pragma unroll
        for (int ks = 0; ks < 16; ks++) {
            const int c = ks * 2 + khalf;
            uint32_t a[2][4];
#pragma unroll
            for (int mi = 0; mi < 2; mi++)
                ldsm_x4(a[mi][0], a[mi][1], a[mi][2], a[mi][3],
                        a_base[mi] + ((c ^ a_s7[mi]) << 4));
            uint32_t b2[4][2];
#pragma unroll
            for (int p = 0; p < 2; p++) {
                uint32_t r0, r1, r2, r3;
                ldsm_x4(r0, r1, r2, r3,
                        bbase + b_off[p] + ((c ^ b_s7[p]) << 4));
                b2[p * 2][0]     = r0; b2[p * 2][1]     = r2;
                b2[p * 2 + 1][0] = r1; b2[p * 2 + 1][1] = r3;
            }
#pragma unroll
            for (int mi = 0; mi < 2; mi++)
#pragma unroll
                for (int nt = 0; nt < 4; nt++)
                    mma16816(acc[mi][nt], a[mi], b2[nt]);
        }
        if (lane == 0) mbar_arrive(mb + 16 + b * 8);  // this warp done with buf b

        // refill buf b for chunk ci+2 BEFORE the epilogue: the bulk copy's
        // latency then overlaps the whole CTA's epilogue work.
        if (ci < 30 && tid == 0) {
            wait_parity(mb + 16 + b * 8, ph);      // all warps drained buf b
            expect_tx(mb + b * 8, 65536);
            bulk_cp(b_sm + b * BUF_SZ, cbB + (size_t)(ci + 2) * 32768,
                    65536, mb + b * 8);
        }

        // epilogue: pairwise-min + exact-key top-2 (13 ops/pair)
        const int innerbase = 2 * (lane & 3);
#pragma unroll
        for (int nt = 0; nt < 4; nt++) {
            const int col = ci * 128 + warpN * 32 + innerbase + nt * 8;
            float2 c2v = *reinterpret_cast<const float2*>(c2s + col);
#pragma unroll
            for (int mi = 0; mi < 2; mi++)
#pragma unroll
                for (int h = 0; h < 2; h++) {
                    float s0 = fmaf(-2.f, acc[mi][nt][h * 2 + 0], c2v.x);
                    float s1 = fmaf(-2.f, acc[mi][nt][h * 2 + 1], c2v.y);
                    float    pmn = fminf(s0, s1);
                    unsigned pid = (s0 <= s1) ? (unsigned)col
                                              : (unsigned)(col + 1);
                    const int s = mi * 2 + h;
                    ins2f(pmn, pid, t0[s], i0[s], t1[s], i1[s]);
                }
        }
    }

    // quad merge (lanes sharing the same token rows); stage 2 cands per warpN
#pragma unroll
    for (int s = 0; s < 4; s++) {
        float    a0 = t0[s], a1 = t1[s];
        unsigned b0 = i0[s], b1 = i1[s];
#pragma unroll
        for (int o = 1; o <= 2; o <<= 1) {
            float    q0  = __shfl_xor_sync(0xFFFFFFFFu, a0, o);
            unsigned qi0 = __shfl_xor_sync(0xFFFFFFFFu, b0, o);
            float    q1  = __shfl_xor_sync(0xFFFFFFFFu, a1, o);
            unsigned qi1 = __shfl_xor_sync(0xFFFFFFFFu, b1, o);
            ins2f(q0, qi0, a0, b0, a1, b1);
            ins2f(q1, qi1, a0, b0, a1, b1);
        }
        if ((lane & 3) == 0) {
            int ltok = warpM * 32 + (s >> 1) * 16 + (s & 1) * 8 + (lane >> 2);
            cand_sm[ltok * 8 + warpN * 2]     = b0;
            cand_sm[ltok * 8 + warpN * 2 + 1] = b1;
        }
    }
    __syncthreads();

    // -------- fused tail: exact fp32 rescore + update; warp -> 8 tokens -----
    const float* cbL  = cbF + (size_t)layer * K * D;
    const float* rsrc = (layer == 0) ? x : g_res;    // residual source
#pragma unroll 1
    for (int tt = 0; tt < 8; tt++) {
        const int ltok  = wid * 8 + tt;
        const int token = tokbase + ltok;
        unsigned mycode = cand_sm[ltok * 8 + (lane & 7)];

        const float* rp = rsrc + (size_t)token * D + lane * 8;
        float4 r0 = *reinterpret_cast<const float4*>(rp);
        float4 r1 = *reinterpret_cast<const float4*>(rp + 4);

        unsigned long long best = ~0ull;
#pragma unroll
        for (int half = 0; half < 2; half++) {
            int codes[4];
            float4 c0[4], c1[4];
#pragma unroll
            for (int j = 0; j < 4; j++) {
                codes[j] = (int)__shfl_sync(0xFFFFFFFFu, mycode, half * 4 + j);
                const float* c = cbL + (size_t)codes[j] * D + lane * 8;
                c0[j] = *reinterpret_cast<const float4*>(c);
                c1[j] = *reinterpret_cast<const float4*>(c + 4);
            }
            float dot[4];
#pragma unroll
            for (int j = 0; j < 4; j++) {
                float d0 = r0.x * c0[j].x;
                d0 = fmaf(r0.y, c0[j].y, d0); d0 = fmaf(r0.z, c0[j].z, d0);
                d0 = fmaf(r0.w, c0[j].w, d0); d0 = fmaf(r1.x, c1[j].x, d0);
                d0 = fmaf(r1.y, c1[j].y, d0); d0 = fmaf(r1.z, c1[j].z, d0);
                d0 = fmaf(r1.w, c1[j].w, d0);
                dot[j] = d0;
            }
#pragma unroll
            for (int o = 16; o; o >>= 1)
#pragma unroll
                for (int j = 0; j < 4; j++)
                    dot[j] += __shfl_xor_sync(0xFFFFFFFFu, dot[j], o);
#pragma unroll
            for (int j = 0; j < 4; j++) {
                float score = fmaf(-2.f, dot[j], g_c2[layer * K + codes[j]]);
                unsigned long long key = pack_key(score, codes[j]);
                best = key < best ? key : best;
            }
        }
        int idx = (int)(unsigned)(best & 0xFFFFFFFFull);

        // update: r -= codeword
        const float* q = cbL + (size_t)idx * D + lane * 8;
        float4 q0 = *reinterpret_cast<const float4*>(q);
        float4 q1 = *reinterpret_cast<const float4*>(q + 4);
        r0.x -= q0.x; r0.y -= q0.y; r0.z -= q0.z; r0.w -= q0.w;
        r1.x -= q1.x; r1.y -= q1.y; r1.z -= q1.z; r1.w -= q1.w;

        if (layer < Q - 1) {
            float* wp = g_res + (size_t)token * D + lane * 8;
            *reinterpret_cast<float4*>(wp)     = r0;
            *reinterpret_cast<float4*>(wp + 4) = r1;
            *reinterpret_cast<uint4*>(
                reinterpret_cast<char*>(g_rb) + sw_off(token, lane)) =
                pack8(r0, r1);
        } else {
            // quantized_out = x - residual_final, written directly
            const float* xp = x + (size_t)token * D + lane * 8;
            float4 x0 = *reinterpret_cast<const float4*>(xp);
            float4 x1 = *reinterpret_cast<const float4*>(xp + 4);
            float4 o0, o1;
            o0.x = x0.x - r0.x; o0.y = x0.y - r0.y;
            o0.z = x0.z - r0.z; o0.w = x0.w - r0.w;
            o1.x = x1.x - r1.x; o1.y = x1.y - r1.y;
            o1.z = x1.z - r1.z; o1.w = x1.w - r1.w;
            float* op = out + (size_t)token * D + lane * 8;
            *reinterpret_cast<float4*>(op)     = o0;
            *reinterpret_cast<float4*>(op + 4) = o1;
        }
        float local = r0.x * r0.x + r0.y * r0.y + r0.z * r0.z + r0.w * r0.w
                    + r1.x * r1.x + r1.y * r1.y + r1.z * r1.z + r1.w * r1.w;
#pragma unroll
        for (int o = 16; o; o >>= 1)
            local += __shfl_down_sync(0xFFFFFFFFu, local, o);
        if (!lane) {
            out[idx_base + layer * n_tok + token] = (float)idx;
            loss_sm[ltok] = local;
        }
    }
    __syncthreads();
    if (wid == 0) {
        float s = loss_sm[lane] + loss_sm[lane + 32]
                + loss_sm[lane + 64] + loss_sm[lane + 96];
#pragma unroll
        for (int o = 16; o; o >>= 1) s += __shfl_down_sync(0xFFFFFFFFu, s, o);
        if (!lane) atomicAdd(&g_loss[layer], s);
    }
}

// ---------------------------------------------------------------------------
__global__ void loss_kernel(float* __restrict__ out, int loss_off, float invND) {
    if (threadIdx.x < Q)
        out[loss_off + threadIdx.x] = g_loss[threadIdx.x] * invND;
}

// ---------------------------------------------------------------------------
extern "C" void kernel_launch(void* const* d_in, const int* in_sizes, int n_in,
                              void* d_out, int out_size) {
    const float* x  = (const float*)d_in[0];   // [8, 4096, 256] fp32
    const float* cb = (const float*)d_in[1];   // [4, 4096, 256] fp32
    float* out = (float*)d_out;

    int nx    = in_sizes[0];      // 8388608
    int n_tok = nx / D;           // 32768
    int ngrp  = nx / 8;

    cudaFuncSetAttribute(coarse_kernel,
                         cudaFuncAttributeMaxDynamicSharedMemorySize, SMEM_SZ);

    init_rb_kernel<<<(ngrp + 255) / 256, 256>>>(x, ngrp);
    c2_split_kernel<<<(Q * K) / 8, 256>>>(cb);

    for (int qi = 0; qi < Q; qi++)
        coarse_kernel<<<n_tok / 128, CTHREADS, SMEM_SZ>>>(cb, x, out, qi,
                                                          n_tok, nx);

    loss_kernel<<<1, 32>>>(out, nx + Q * n_tok, 1.f / (float)nx);
}

// round 17
// speedup vs baseline: 1.1936x; 1.1369x over previous
#include <cuda_runtime.h>
#include <cuda_bf16.h>
#include <cstdint>

#define Q  4
#define K  4096
#define D  256
#define NTOK_MAX 32768
#define NX_MAX   (NTOK_MAX * D)
#define CB_ELEMS (Q * K * D)
#define SCORE_OFFSET 1024.0f
#define NBLK_MAX 256

// ---------------- device scratch (allocation-free rule) ----------------
__device__ float                             g_res[NX_MAX];   // fp32 linear
__device__ __align__(16) __nv_bfloat16       g_rb[NX_MAX];    // bf16 swizzled
__device__ __align__(16) __nv_bfloat16       g_cbb[CB_ELEMS]; // bf16 swizzled
__device__ float                             g_c2[Q * K];
__device__ float                             g_loss[Q];
__device__ int                               g_flag[NBLK_MAX]; // layers done/blk

// ---------------- helpers ----------------
__device__ __forceinline__ uint32_t smem_u32(const void* p) {
    uint32_t a;
    asm("{ .reg .u64 t; cvta.to.shared.u64 t, %1; cvt.u32.u64 %0, t; }"
        : "=r"(a) : "l"(p));
    return a;
}
__device__ __forceinline__ unsigned long long pack_key(float s, int code) {
    unsigned u = __float_as_uint(s);
    u = (u & 0x80000000u) ? ~u : (u | 0x80000000u);
    return ((unsigned long long)u << 32) | (unsigned)code;
}
__device__ __forceinline__ int ld_acq(const int* p) {
    int v;
    asm volatile("ld.acquire.gpu.b32 %0, [%1];" : "=r"(v) : "l"(p) : "memory");
    return v;
}
__device__ __forceinline__ void mbar_init(uint32_t m, uint32_t cnt) {
    asm volatile("mbarrier.init.shared.b64 [%0], %1;" :: "r"(m), "r"(cnt) : "memory");
}
__device__ __forceinline__ void mbar_arrive(uint32_t m) {
    asm volatile("mbarrier.arrive.shared.b64 _, [%0];" :: "r"(m) : "memory");
}
__device__ __forceinline__ void expect_tx(uint32_t m, uint32_t bytes) {
    asm volatile("mbarrier.arrive.expect_tx.shared.b64 _, [%0], %1;"
                 :: "r"(m), "r"(bytes) : "memory");
}
__device__ __forceinline__ void bulk_cp(uint32_t dst, const void* src,
                                        uint32_t bytes, uint32_t mbar) {
    asm volatile(
        "cp.async.bulk.shared::cta.global.mbarrier::complete_tx::bytes "
        "[%0], [%1], %2, [%3];"
        :: "r"(dst), "l"(src), "r"(bytes), "r"(mbar) : "memory");
}
__device__ __forceinline__ void wait_parity(uint32_t m, uint32_t ph) {
    asm volatile(
        "{\n\t.reg .pred P;\n\t"
        "W%=:\n\t"
        "mbarrier.try_wait.parity.acquire.cta.shared::cta.b64 P, [%0], %1, 0x989680;\n\t"
        "@P bra D%=;\n\t"
        "bra W%=;\n\t"
        "D%=:\n\t}"
        :: "r"(m), "r"(ph) : "memory");
}
__device__ __forceinline__ void ldsm_x4(uint32_t& r0, uint32_t& r1,
                                        uint32_t& r2, uint32_t& r3, uint32_t a) {
    asm volatile("ldmatrix.sync.aligned.m8n8.x4.shared.b16 {%0,%1,%2,%3}, [%4];"
                 : "=r"(r0), "=r"(r1), "=r"(r2), "=r"(r3) : "r"(a));
}
__device__ __forceinline__ void mma16816(float* d, const uint32_t* a,
                                         const uint32_t* b) {
    asm volatile(
        "mma.sync.aligned.m16n8k16.row.col.f32.bf16.bf16.f32 "
        "{%0,%1,%2,%3},{%4,%5,%6,%7},{%8,%9},{%0,%1,%2,%3};"
        : "+f"(d[0]), "+f"(d[1]), "+f"(d[2]), "+f"(d[3])
        : "r"(a[0]), "r"(a[1]), "r"(a[2]), "r"(a[3]), "r"(b[0]), "r"(b[1]));
}
__device__ __forceinline__ uint4 pack8(float4 a, float4 b) {
    __nv_bfloat162 p0 = __floats2bfloat162_rn(a.x, a.y);
    __nv_bfloat162 p1 = __floats2bfloat162_rn(a.z, a.w);
    __nv_bfloat162 p2 = __floats2bfloat162_rn(b.x, b.y);
    __nv_bfloat162 p3 = __floats2bfloat162_rn(b.z, b.w);
    uint4 r;
    r.x = *reinterpret_cast<uint32_t*>(&p0);
    r.y = *reinterpret_cast<uint32_t*>(&p1);
    r.z = *reinterpret_cast<uint32_t*>(&p2);
    r.w = *reinterpret_cast<uint32_t*>(&p3);
    return r;
}
// 128-row-block swizzled offset (row, c16 = 16B column group 0..31)
__device__ __forceinline__ uint32_t sw_off(int row, int c16) {
    return (uint32_t)((row >> 7) * 65536) + (uint32_t)((row & 127) * 512)
         + (uint32_t)(((c16 ^ (row & 7)) << 4));
}
__device__ __forceinline__ void ins2f(float k, unsigned id,
                                      float& t0, unsigned& i0,
                                      float& t1, unsigned& i1) {
    bool p0 = k < t0;
    bool p1 = k < t1;
    float    nt1 = p1 ? k  : t1;
    unsigned ni1 = p1 ? id : i1;
    t1 = p0 ? t0 : nt1;
    i1 = p0 ? i0 : ni1;
    t0 = fminf(t0, k);
    i0 = p0 ? id : i0;
}

// ---------------------------------------------------------------------------
// bf16 swizzled mirror of x + flag reset
__global__ void init_rb_kernel(const float* __restrict__ x, int ngrp) {
    int i = blockIdx.x * blockDim.x + threadIdx.x;
    if (blockIdx.x == 0 && threadIdx.x < NBLK_MAX) g_flag[threadIdx.x] = 0;
    if (i >= ngrp) return;
    float4 v0 = reinterpret_cast<const float4*>(x)[i * 2];
    float4 v1 = reinterpret_cast<const float4*>(x)[i * 2 + 1];
    int t = i >> 5, c = i & 31;
    *reinterpret_cast<uint4*>(reinterpret_cast<char*>(g_rb) + sw_off(t, c)) =
        pack8(v0, v1);
}

// exact ||c||^2 + swizzled bf16 codebook, one warp per row; zero losses
__global__ void c2_split_kernel(const float* __restrict__ cb) {
    if (blockIdx.x == 0 && threadIdx.x < Q) g_loss[threadIdx.x] = 0.f;
    int row  = blockIdx.x * 8 + (threadIdx.x >> 5);
    int lane = threadIdx.x & 31;
    const float* p = cb + (size_t)row * D + lane * 8;
    float4 v0 = *reinterpret_cast<const float4*>(p);
    float4 v1 = *reinterpret_cast<const float4*>(p + 4);
    *reinterpret_cast<uint4*>(reinterpret_cast<char*>(g_cbb) + sw_off(row, lane)) =
        pack8(v0, v1);
    float s = v0.x * v0.x + v0.y * v0.y + v0.z * v0.z + v0.w * v0.w
            + v1.x * v1.x + v1.y * v1.y + v1.z * v1.z + v1.w * v1.w;
#pragma unroll
    for (int o = 16; o; o >>= 1) s += __shfl_down_sync(0xFFFFFFFFu, s, o);
    if (!lane) g_c2[row] = s;
}

// ---------------------------------------------------------------------------
// Fused coarse + rescore + update, ALL LAYERS IN ONE LAUNCH.
// grid = Q * (n_tok/128); layer = bid / nblk. Cross-layer dependency is
// per-token-block: consumer spins on g_flag[block] (acquire) before copying
// its A tile; producer releases after its tail writes g_res/g_rb.
#define A_OFF    16384
#define B_OFF    (A_OFF + 65536)
#define BUF_SZ   65536
#define MB_OFF   (B_OFF + 2 * BUF_SZ)
#define CAND_OFF (MB_OFF + 64)
#define LOSS_OFF (CAND_OFF + 128 * 8 * 4)
#define SMEM_SZ  (LOSS_OFF + 128 * 4)
#define CTHREADS 512

__global__ __launch_bounds__(CTHREADS, 1)
void coarse_kernel(const float* __restrict__ cbF, const float* __restrict__ x,
                   float* __restrict__ out, int n_tok, int idx_base) {
    extern __shared__ char smem[];
    const int tid  = threadIdx.x;
    const int lane = tid & 31, wid = tid >> 5;
    const int warpM = wid >> 2, warpN = wid & 3;
    const int nblk  = n_tok >> 7;
    const int layer = blockIdx.x / nblk;
    const int block = blockIdx.x - layer * nblk;
    const int tokbase = block * 128;

    const uint32_t sb   = smem_u32(smem);
    const uint32_t a_sm = sb + A_OFF;
    const uint32_t b_sm = sb + B_OFF;
    const uint32_t mb   = sb + MB_OFF;  // fill0, fill1, drain0, drain1, ambar
    float*    c2s     = reinterpret_cast<float*>(smem);
    unsigned* cand_sm = reinterpret_cast<unsigned*>(smem + CAND_OFF);
    float*    loss_sm = reinterpret_cast<float*>(smem + LOSS_OFF);

    const __nv_bfloat16* cbB = g_cbb + (size_t)layer * K * D;  // swizzled

    if (tid == 0) {
        mbar_init(mb + 0, 1);     // fill buf0 (expect_tx)
        mbar_init(mb + 8, 1);     // fill buf1
        mbar_init(mb + 16, 16);   // drain buf0 (16 warps)
        mbar_init(mb + 24, 16);   // drain buf1
        mbar_init(mb + 32, 1);    // A tile
        asm volatile("fence.proxy.async;" ::: "memory");
        // B stream (static codebook): no cross-layer dep, start immediately
        expect_tx(mb + 0, 65536);
        bulk_cp(b_sm, cbB, 65536, mb + 0);
        expect_tx(mb + 8, 65536);
        bulk_cp(b_sm + BUF_SZ, cbB + 32768, 65536, mb + 8);
        // A tile depends on the previous layer's tail for this block
        if (layer > 0) {
            while (ld_acq(&g_flag[block]) < layer) __nanosleep(128);
        }
        expect_tx(mb + 32, 65536);
        bulk_cp(a_sm, g_rb + (size_t)tokbase * D, 65536, mb + 32);
    }
    for (int i = tid; i < 4096; i += CTHREADS)
        c2s[i] = g_c2[layer * K + i] + SCORE_OFFSET;
    __syncthreads();            // also orders tid0's acquire for all threads
    wait_parity(mb + 32, 0);    // A tile resident

    // lane geometry for ldmatrix
    const int lrow  = ((lane >> 3) & 1) * 8 + (lane & 7);
    const int khalf = lane >> 4;
    uint32_t a_base[2]; int a_s7[2];
#pragma unroll
    for (int mi = 0; mi < 2; mi++) {
        int row = warpM * 32 + mi * 16 + lrow;
        a_base[mi] = a_sm + row * 512;
        a_s7[mi]   = row & 7;
    }
    uint32_t b_off[2]; int b_s7[2];
#pragma unroll
    for (int p = 0; p < 2; p++) {
        int row = warpN * 32 + p * 16 + lrow;
        b_off[p] = row * 512;
        b_s7[p]  = row & 7;
    }

    // running top-2 (float keys) + code ids, 4 token-row slots (mi x h)
    float    t0[4], t1[4];
    unsigned i0[4], i1[4];
#pragma unroll
    for (int s = 0; s < 4; s++) {
        t0[s] = __int_as_float(0x7f800000);
        t1[s] = __int_as_float(0x7f800000);
        i0[s] = 0u; i1[s] = 0u;
    }

    for (int ci = 0; ci < 32; ci++) {
        const int b  = ci & 1;
        const uint32_t ph = (unsigned)((ci >> 1) & 1);

        wait_parity(mb + b * 8, ph);               // chunk ci data resident

        const uint32_t bbase = b_sm + b * BUF_SZ;
        float acc[2][4][4];
#pragma unroll
        for (int mi = 0; mi < 2; mi++)
#pragma unroll
            for (int nt = 0; nt < 4; nt++)
#pragma unroll
                for (int v = 0; v < 4; v++) acc[mi][nt][v] = 0.f;

#pragma unroll
        for (int ks = 0; ks < 16; ks++) {
            const int c = ks * 2 + khalf;
            uint32_t a[2][4];
#pragma unroll
            for (int mi = 0; mi < 2; mi++)
                ldsm_x4(a[mi][0], a[mi][1], a[mi][2], a[mi][3],
                        a_base[mi] + ((c ^ a_s7[mi]) << 4));
            uint32_t b2[4][2];
#pragma unroll
            for (int p = 0; p < 2; p++) {
                uint32_t r0, r1, r2, r3;
                ldsm_x4(r0, r1, r2, r3,
                        bbase + b_off[p] + ((c ^ b_s7[p]) << 4));
                b2[p * 2][0]     = r0; b2[p * 2][1]     = r2;
                b2[p * 2 + 1][0] = r1; b2[p * 2 + 1][1] = r3;
            }
#pragma unroll
            for (int mi = 0; mi < 2; mi++)
#pragma unroll
                for (int nt = 0; nt < 4; nt++)
                    mma16816(acc[mi][nt], a[mi], b2[nt]);
        }
        if (lane == 0) mbar_arrive(mb + 16 + b * 8);  // this warp done with buf b

        // refill buf b for chunk ci+2 before the epilogue (latency overlap)
        if (ci < 30 && tid == 0) {
            wait_parity(mb + 16 + b * 8, ph);      // all warps drained buf b
            expect_tx(mb + b * 8, 65536);
            bulk_cp(b_sm + b * BUF_SZ, cbB + (size_t)(ci + 2) * 32768,
                    65536, mb + b * 8);
        }

        // epilogue: pairwise-min + exact-key top-2 (13 ops/pair)
        const int innerbase = 2 * (lane & 3);
#pragma unroll
        for (int nt = 0; nt < 4; nt++) {
            const int col = ci * 128 + warpN * 32 + innerbase + nt * 8;
            float2 c2v = *reinterpret_cast<const float2*>(c2s + col);
#pragma unroll
            for (int mi = 0; mi < 2; mi++)
#pragma unroll
                for (int h = 0; h < 2; h++) {
                    float s0 = fmaf(-2.f, acc[mi][nt][h * 2 + 0], c2v.x);
                    float s1 = fmaf(-2.f, acc[mi][nt][h * 2 + 1], c2v.y);
                    float    pmn = fminf(s0, s1);
                    unsigned pid = (s0 <= s1) ? (unsigned)col
                                              : (unsigned)(col + 1);
                    const int s = mi * 2 + h;
                    ins2f(pmn, pid, t0[s], i0[s], t1[s], i1[s]);
                }
        }
    }

    // quad merge (lanes sharing the same token rows); stage 2 cands per warpN
#pragma unroll
    for (int s = 0; s < 4; s++) {
        float    a0 = t0[s], a1 = t1[s];
        unsigned b0 = i0[s], b1 = i1[s];
#pragma unroll
        for (int o = 1; o <= 2; o <<= 1) {
            float    q0  = __shfl_xor_sync(0xFFFFFFFFu, a0, o);
            unsigned qi0 = __shfl_xor_sync(0xFFFFFFFFu, b0, o);
            float    q1  = __shfl_xor_sync(0xFFFFFFFFu, a1, o);
            unsigned qi1 = __shfl_xor_sync(0xFFFFFFFFu, b1, o);
            ins2f(q0, qi0, a0, b0, a1, b1);
            ins2f(q1, qi1, a0, b0, a1, b1);
        }
        if ((lane & 3) == 0) {
            int ltok = warpM * 32 + (s >> 1) * 16 + (s & 1) * 8 + (lane >> 2);
            cand_sm[ltok * 8 + warpN * 2]     = b0;
            cand_sm[ltok * 8 + warpN * 2 + 1] = b1;
        }
    }
    __syncthreads();

    // -------- fused tail: exact fp32 rescore + update; warp -> 8 tokens -----
    const float* cbL  = cbF + (size_t)layer * K * D;
    const float* rsrc = (layer == 0) ? x : g_res;    // residual source
#pragma unroll 1
    for (int tt = 0; tt < 8; tt++) {
        const int ltok  = wid * 8 + tt;
        const int token = tokbase + ltok;
        unsigned mycode = cand_sm[ltok * 8 + (lane & 7)];

        const float* rp = rsrc + (size_t)token * D + lane * 8;
        float4 r0 = *reinterpret_cast<const float4*>(rp);
        float4 r1 = *reinterpret_cast<const float4*>(rp + 4);

        unsigned long long best = ~0ull;
#pragma unroll
        for (int half = 0; half < 2; half++) {
            int codes[4];
            float4 c0[4], c1[4];
#pragma unroll
            for (int j = 0; j < 4; j++) {
                codes[j] = (int)__shfl_sync(0xFFFFFFFFu, mycode, half * 4 + j);
                const float* c = cbL + (size_t)codes[j] * D + lane * 8;
                c0[j] = *reinterpret_cast<const float4*>(c);
                c1[j] = *reinterpret_cast<const float4*>(c + 4);
            }
            float dot[4];
#pragma unroll
            for (int j = 0; j < 4; j++) {
                float d0 = r0.x * c0[j].x;
                d0 = fmaf(r0.y, c0[j].y, d0); d0 = fmaf(r0.z, c0[j].z, d0);
                d0 = fmaf(r0.w, c0[j].w, d0); d0 = fmaf(r1.x, c1[j].x, d0);
                d0 = fmaf(r1.y, c1[j].y, d0); d0 = fmaf(r1.z, c1[j].z, d0);
                d0 = fmaf(r1.w, c1[j].w, d0);
                dot[j] = d0;
            }
#pragma unroll
            for (int o = 16; o; o >>= 1)
#pragma unroll
                for (int j = 0; j < 4; j++)
                    dot[j] += __shfl_xor_sync(0xFFFFFFFFu, dot[j], o);
#pragma unroll
            for (int j = 0; j < 4; j++) {
                float score = fmaf(-2.f, dot[j], g_c2[layer * K + codes[j]]);
                unsigned long long key = pack_key(score, codes[j]);
                best = key < best ? key : best;
            }
        }
        int idx = (int)(unsigned)(best & 0xFFFFFFFFull);

        // update: r -= codeword
        const float* q = cbL + (size_t)idx * D + lane * 8;
        float4 q0 = *reinterpret_cast<const float4*>(q);
        float4 q1 = *reinterpret_cast<const float4*>(q + 4);
        r0.x -= q0.x; r0.y -= q0.y; r0.z -= q0.z; r0.w -= q0.w;
        r1.x -= q1.x; r1.y -= q1.y; r1.z -= q1.z; r1.w -= q1.w;

        if (layer < Q - 1) {
            float* wp = g_res + (size_t)token * D + lane * 8;
            *reinterpret_cast<float4*>(wp)     = r0;
            *reinterpret_cast<float4*>(wp + 4) = r1;
            *reinterpret_cast<uint4*>(
                reinterpret_cast<char*>(g_rb) + sw_off(token, lane)) =
                pack8(r0, r1);
        } else {
            // quantized_out = x - residual_final, written directly
            const float* xp = x + (size_t)token * D + lane * 8;
            float4 x0 = *reinterpret_cast<const float4*>(xp);
            float4 x1 = *reinterpret_cast<const float4*>(xp + 4);
            float4 o0, o1;
            o0.x = x0.x - r0.x; o0.y = x0.y - r0.y;
            o0.z = x0.z - r0.z; o0.w = x0.w - r0.w;
            o1.x = x1.x - r1.x; o1.y = x1.y - r1.y;
            o1.z = x1.z - r1.z; o1.w = x1.w - r1.w;
            float* op = out + (size_t)token * D + lane * 8;
            *reinterpret_cast<float4*>(op)     = o0;
            *reinterpret_cast<float4*>(op + 4) = o1;
        }
        float local = r0.x * r0.x + r0.y * r0.y + r0.z * r0.z + r0.w * r0.w
                    + r1.x * r1.x + r1.y * r1.y + r1.z * r1.z + r1.w * r1.w;
#pragma unroll
        for (int o = 16; o; o >>= 1)
            local += __shfl_down_sync(0xFFFFFFFFu, local, o);
        if (!lane) {
            out[idx_base + layer * n_tok + token] = (float)idx;
            loss_sm[ltok] = local;
        }
    }
    // release the flag for the next layer: writes must be GPU-visible first
    if (layer < Q - 1) {
        __threadfence();
        asm volatile("fence.proxy.async;" ::: "memory");
    }
    __syncthreads();
    if (layer < Q - 1 && tid == 0)
        atomicExch(&g_flag[block], layer + 1);
    if (wid == 0) {
        float s = loss_sm[lane] + loss_sm[lane + 32]
                + loss_sm[lane + 64] + loss_sm[lane + 96];
#pragma unroll
        for (int o = 16; o; o >>= 1) s += __shfl_down_sync(0xFFFFFFFFu, s, o);
        if (!lane) atomicAdd(&g_loss[layer], s);
    }
}

// ---------------------------------------------------------------------------
__global__ void loss_kernel(float* __restrict__ out, int loss_off, float invND) {
    if (threadIdx.x < Q)
        out[loss_off + threadIdx.x] = g_loss[threadIdx.x] * invND;
}

// ---------------------------------------------------------------------------
extern "C" void kernel_launch(void* const* d_in, const int* in_sizes, int n_in,
                              void* d_out, int out_size) {
    const float* x  = (const float*)d_in[0];   // [8, 4096, 256] fp32
    const float* cb = (const float*)d_in[1];   // [4, 4096, 256] fp32
    float* out = (float*)d_out;

    int nx    = in_sizes[0];      // 8388608
    int n_tok = nx / D;           // 32768
    int ngrp  = nx / 8;

    cudaFuncSetAttribute(coarse_kernel,
                         cudaFuncAttributeMaxDynamicSharedMemorySize, SMEM_SZ);

    init_rb_kernel<<<(ngrp + 255) / 256, 256>>>(x, ngrp);
    c2_split_kernel<<<(Q * K) / 8, 256>>>(cb);

    coarse_kernel<<<Q * (n_tok / 128), CTHREADS, SMEM_SZ>>>(cb, x, out,
                                                            n_tok, nx);

    loss_kernel<<<1, 32>>>(out, nx + Q * n_tok, 1.f / (float)nx);
}